// round 16
// baseline (speedup 1.0000x reference)
#include <cuda_runtime.h>
#include <cuda_fp16.h>
#include <math.h>
#include <stdint.h>

#define NROWS 8192
#define DIM   1024
#define BM    128
#define BN    128
#define BK    64                              // fp16 elems per chunk (128 B rows)
#define NSTAGE 3
#define NITER (DIM / BK)                      // 16
#define JT    (NROWS / BN)                    // 64
#define NFBLK (NROWS / 128)                   // 64 finalize blocks
#define STAGE_A_BYTES (BM * BK * 2)           // 16384
#define STAGE_BYTES   (2 * STAGE_A_BYTES)     // 32768
#define SMEM_TOTAL    (NSTAGE * STAGE_BYTES)  // 98304
#define LOG2E 1.4426950408889634f
#define LN2   0.6931471805599453f

// ---------------- device scratch ----------------
__device__ __align__(1024) __half g_zh[2 * NROWS * DIM];
__device__ float g_diag[NROWS];               // stores log2e-scaled cosine (f32)
__device__ float g_pe[(size_t)JT * NROWS];
__device__ float g_bl[NFBLK];
__device__ float g_bp[NFBLK];
__device__ unsigned int g_cnt;

// ---------------- PTX helpers ----------------
__device__ __forceinline__ uint32_t smem_u32(const void* p) {
    uint32_t a;
    asm("{ .reg .u64 t; cvta.to.shared.u64 t, %1; cvt.u32.u64 %0, t; }" : "=r"(a) : "l"(p));
    return a;
}
#define CPA16(dst, src) \
    asm volatile("cp.async.cg.shared.global [%0], [%1], 16;" :: "r"(dst), "l"(src) : "memory")
#define CPA_COMMIT() asm volatile("cp.async.commit_group;" ::: "memory")
#define CPA_WAIT1()  asm volatile("cp.async.wait_group 1;" ::: "memory")
#define CPA_WAIT0()  asm volatile("cp.async.wait_group 0;" ::: "memory")

__device__ __forceinline__ void ldsm4(uint32_t* r, uint32_t addr) {
    asm volatile("ldmatrix.sync.aligned.m8n8.x4.shared.b16 {%0,%1,%2,%3}, [%4];"
        : "=r"(r[0]), "=r"(r[1]), "=r"(r[2]), "=r"(r[3]) : "r"(addr));
}
__device__ __forceinline__ void mma16816(float* d, const uint32_t* a, const uint32_t* b) {
    asm volatile(
        "mma.sync.aligned.m16n8k16.row.col.f32.f16.f16.f32 "
        "{%0,%1,%2,%3}, {%4,%5,%6,%7}, {%8,%9}, {%0,%1,%2,%3};"
        : "+f"(d[0]), "+f"(d[1]), "+f"(d[2]), "+f"(d[3])
        : "r"(a[0]), "r"(a[1]), "r"(a[2]), "r"(a[3]), "r"(b[0]), "r"(b[1]));
}

// ---------------------------------------------------------------------------
// 1) Fused norms + convert to pre-normalized fp16.
//    x1 rows (row < NROWS) are additionally scaled by log2(e) so the MMA
//    output is log2e*cos and the epilogue exp is a bare ex2.
// ---------------------------------------------------------------------------
__global__ __launch_bounds__(256) void normconv_kernel(const float* __restrict__ z) {
    if (blockIdx.x == 0 && threadIdx.x == 0) g_cnt = 0;
    int warp = threadIdx.x >> 5, lane = threadIdx.x & 31;
    int row  = blockIdx.x * 8 + warp;
    const float* p = z + (size_t)row * DIM;
    float4 v[8];
    float s = 0.f;
    #pragma unroll
    for (int seg = 0; seg < 4; seg++) {
        #pragma unroll
        for (int h = 0; h < 2; h++) {
            float4 t = *reinterpret_cast<const float4*>(p + seg * 256 + lane * 8 + h * 4);
            v[seg * 2 + h] = t;
            s += t.x * t.x + t.y * t.y + t.z * t.z + t.w * t.w;
        }
    }
    #pragma unroll
    for (int o = 16; o; o >>= 1) s += __shfl_xor_sync(0xffffffffu, s, o);
    float inv = rsqrtf(s);
    if (row < NROWS) inv *= LOG2E;             // fold exp's log2e into x1
    __half* ob = g_zh + (size_t)row * DIM;
    #pragma unroll
    for (int seg = 0; seg < 4; seg++) {
        uint4 pk;
        __half2 h0 = __floats2half2_rn(v[seg*2].x * inv,   v[seg*2].y * inv);
        __half2 h1 = __floats2half2_rn(v[seg*2].z * inv,   v[seg*2].w * inv);
        __half2 h2 = __floats2half2_rn(v[seg*2+1].x * inv, v[seg*2+1].y * inv);
        __half2 h3 = __floats2half2_rn(v[seg*2+1].z * inv, v[seg*2+1].w * inv);
        pk.x = *reinterpret_cast<uint32_t*>(&h0);
        pk.y = *reinterpret_cast<uint32_t*>(&h1);
        pk.z = *reinterpret_cast<uint32_t*>(&h2);
        pk.w = *reinterpret_cast<uint32_t*>(&h3);
        *reinterpret_cast<uint4*>(ob + seg * 256 + lane * 8) = pk;
    }
}

// ---------------------------------------------------------------------------
// 2) HMMA GEMM 128x128x64/iter, 3-stage cp.async, single sync per iter.
//    Epilogue: f16x2 ex2 (h2exp2) + HADD2 accumulation — half the MUFU ops,
//    ~44% fewer epilogue instructions. Split diag/non-diag paths.
// ---------------------------------------------------------------------------
__global__ __launch_bounds__(256, 2) void gemm_kernel() {
    extern __shared__ char smem[];
    const uint32_t sb = smem_u32(smem);
    const int tid = threadIdx.x;
    const int warp = tid >> 5, lane = tid & 31;
    const int wy = warp >> 2, wx = warp & 3;        // 2 x 4 warp grid
    const int bi = blockIdx.y, bj = blockIdx.x;

    const char* Ag = (const char*)(g_zh + (size_t)bi * BM * DIM);
    const char* Bg = (const char*)(g_zh + (size_t)(NROWS + bj * BN) * DIM);

    // cp.async mapping: 128B rows = 8 x 16B chunks; phys = ch ^ (row & 7).
    const int row0 = tid >> 3, ch0 = tid & 7;       // rows 0..31
    uint32_t s_off[4];
    size_t   g_off[4];
    #pragma unroll
    for (int r = 0; r < 4; r++) {
        int row = row0 + r * 32;
        int ph  = ch0 ^ (row & 7);
        s_off[r] = row * 128 + ph * 16;
        g_off[r] = (size_t)row * DIM * 2 + ch0 * 16;
    }

    float acc[4][4][4];
    #pragma unroll
    for (int mt = 0; mt < 4; mt++)
        #pragma unroll
        for (int nt = 0; nt < 4; nt++)
            #pragma unroll
            for (int q = 0; q < 4; q++) acc[mt][nt][q] = 0.f;

    // prologue: stages 0,1
    #pragma unroll
    for (int s = 0; s < NSTAGE - 1; s++) {
        uint32_t As = sb + s * STAGE_BYTES;
        uint32_t Bs = As + STAGE_A_BYTES;
        size_t kb = (size_t)(s * BK) * 2;
        #pragma unroll
        for (int r = 0; r < 4; r++) {
            CPA16(As + s_off[r], Ag + g_off[r] + kb);
            CPA16(Bs + s_off[r], Bg + g_off[r] + kb);
        }
        CPA_COMMIT();
    }

    // ldmatrix lane components
    const int rl  = lane & 15;                  // A row within 16
    const int ahi = lane >> 4;                  // A 16B k-chunk select
    const int nl  = (lane & 7) | ((lane >> 4) << 3);   // B n within 16
    const int bhi = (lane >> 3) & 1;

    for (int kc = 0; kc < NITER; kc++) {
        const int st = kc % NSTAGE;
        if (kc < NITER - 1) { CPA_WAIT1(); } else { CPA_WAIT0(); }
        __syncthreads();
        if (kc + NSTAGE - 1 < NITER) {
            const int sn = (kc + NSTAGE - 1) % NSTAGE;
            uint32_t As = sb + sn * STAGE_BYTES;
            uint32_t Bs = As + STAGE_A_BYTES;
            size_t kb = (size_t)((kc + NSTAGE - 1) * BK) * 2;
            #pragma unroll
            for (int r = 0; r < 4; r++) {
                CPA16(As + s_off[r], Ag + g_off[r] + kb);
                CPA16(Bs + s_off[r], Bg + g_off[r] + kb);
            }
            CPA_COMMIT();
        }
        const uint32_t As = sb + st * STAGE_BYTES;
        const uint32_t Bs = As + STAGE_A_BYTES;
        #pragma unroll
        for (int ks = 0; ks < 4; ks++) {
            uint32_t a[4][4], b[2][4];
            uint32_t a_addr = As + (wy * 64 + rl) * 128 + (((ks * 2 + ahi) ^ (rl & 7)) * 16);
            #pragma unroll
            for (int mt = 0; mt < 4; mt++) ldsm4(a[mt], a_addr + mt * 2048);
            uint32_t b_addr = Bs + (wx * 32 + nl) * 128 + (((ks * 2 + bhi) ^ (nl & 7)) * 16);
            #pragma unroll
            for (int p = 0; p < 2; p++) ldsm4(b[p], b_addr + p * 2048);
            #pragma unroll
            for (int mt = 0; mt < 4; mt++)
                #pragma unroll
                for (int nt = 0; nt < 4; nt++)
                    mma16816(acc[mt][nt], a[mt], &b[nt >> 1][(nt & 1) * 2]);
        }
    }

    // ---------------- epilogue: f16x2 ex2 row-sums (+ diag on diag tiles) --
    __syncthreads();
    float* sred = (float*)smem;                // 128 rows x 4 wx
    const bool isdiag = (bi == bj);
    #pragma unroll
    for (int mt = 0; mt < 4; mt++) {
        int ra = wy * 64 + mt * 16 + (lane >> 2);
        __half2 hA = __floats2half2_rn(0.f, 0.f);
        __half2 hB = __floats2half2_rn(0.f, 0.f);
        #pragma unroll
        for (int nt = 0; nt < 4; nt++) {
            hA = __hadd2(hA, h2exp2(__floats2half2_rn(acc[mt][nt][0], acc[mt][nt][1])));
            hB = __hadd2(hB, h2exp2(__floats2half2_rn(acc[mt][nt][2], acc[mt][nt][3])));
        }
        if (isdiag) {
            #pragma unroll
            for (int nt = 0; nt < 4; nt++) {
                int c0 = wx * 32 + nt * 8 + 2 * (lane & 3);
                if (ra == c0)         g_diag[bi * BM + ra] = acc[mt][nt][0];
                if (ra == c0 + 1)     g_diag[bi * BM + ra] = acc[mt][nt][1];
                if (ra + 8 == c0)     g_diag[bi * BM + ra + 8] = acc[mt][nt][2];
                if (ra + 8 == c0 + 1) g_diag[bi * BM + ra + 8] = acc[mt][nt][3];
            }
        }
        float sA = __low2float(hA) + __high2float(hA);
        float sB = __low2float(hB) + __high2float(hB);
        sA += __shfl_xor_sync(0xffffffffu, sA, 1);
        sA += __shfl_xor_sync(0xffffffffu, sA, 2);
        sB += __shfl_xor_sync(0xffffffffu, sB, 1);
        sB += __shfl_xor_sync(0xffffffffu, sB, 2);
        if ((lane & 3) == 0) {
            sred[ra * 4 + wx] = sA;
            sred[(ra + 8) * 4 + wx] = sB;
        }
    }
    __syncthreads();
    if (tid < BM) {
        float s = sred[tid * 4 + 0] + sred[tid * 4 + 1]
                + sred[tid * 4 + 2] + sred[tid * 4 + 3];
        g_pe[(size_t)bj * NROWS + bi * BM + tid] = s;
    }
}

// ---------------------------------------------------------------------------
// 3) Finalize (ALPHA=1 -> alpha=p_ij, BETA=0 -> neg_sim drops).
//    pe replicates the epilogue's per-lane f16 pipeline exactly:
//    cvt.rn.f16 -> ex2.approx.f16 -> f32, so the diagonal term cancels to
//    within one HADD2 rounding. pos recovered via * ln2 in full f32.
// ---------------------------------------------------------------------------
__global__ __launch_bounds__(1024) void finalize_kernel(float* __restrict__ out) {
    __shared__ float spart[8][128];
    __shared__ float sl[128], sp[128];
    __shared__ bool is_last;
    int rl = threadIdx.x & 127, tg = threadIdx.x >> 7;
    int r = blockIdx.x * 128 + rl;
    float se = 0.f;
    #pragma unroll
    for (int t = tg * 8; t < tg * 8 + 8; t++) se += g_pe[(size_t)t * NROWS + r];
    spart[tg][rl] = se;
    __syncthreads();
    if (threadIdx.x < 128) {
        float tot = 0.f;
        #pragma unroll
        for (int t = 0; t < 8; t++) tot += spart[t][rl];
        float dv  = g_diag[r];                       // log2e-scaled cosine, f32
        float pe  = __half2float(hexp2(__float2half_rn(dv)));  // matches epilogue lane op
        float pos = dv * LN2;                        // true cosine similarity
        float p   = pe / (tot - pe);
        sl[rl] = -logf(p) - p * pos;
        sp[rl] = p;
    }
    __syncthreads();
    #pragma unroll
    for (int o = 64; o; o >>= 1) {
        if (threadIdx.x < o) {
            sl[threadIdx.x] += sl[threadIdx.x + o];
            sp[threadIdx.x] += sp[threadIdx.x + o];
        }
        __syncthreads();
    }
    if (threadIdx.x == 0) {
        g_bl[blockIdx.x] = sl[0];
        g_bp[blockIdx.x] = sp[0];
        __threadfence();
        unsigned int prev = atomicAdd(&g_cnt, 1u);
        is_last = (prev == NFBLK - 1);
    }
    __syncthreads();
    if (is_last && threadIdx.x == 0) {
        float tl = 0.f, tp = 0.f;
        #pragma unroll
        for (int b = 0; b < NFBLK; b++) { tl += g_bl[b]; tp += g_bp[b]; }
        out[0] = tl / (float)NROWS;
        out[1] = tp / (float)NROWS;
    }
}

// ---------------------------------------------------------------------------
extern "C" void kernel_launch(void* const* d_in, const int* in_sizes, int n_in,
                              void* d_out, int out_size) {
    const float* z = (const float*)d_in[0];
    float* out = (float*)d_out;

    cudaFuncSetAttribute(gemm_kernel, cudaFuncAttributeMaxDynamicSharedMemorySize, SMEM_TOTAL);

    normconv_kernel<<<2 * NROWS / 8, 256>>>(z);
    gemm_kernel<<<dim3(NROWS / BN, NROWS / BM), 256, SMEM_TOTAL>>>();
    finalize_kernel<<<NFBLK, 1024>>>(out);
}

// round 17
// speedup vs baseline: 1.0118x; 1.0118x over previous
#include <cuda_runtime.h>
#include <cuda_fp16.h>
#include <math.h>
#include <stdint.h>

#define NROWS 8192
#define DIM   1024
#define BM    128
#define BN    128
#define BK    64                              // fp16 elems per chunk (128 B rows)
#define NSTAGE 3
#define NITER (DIM / BK)                      // 16
#define JT    (NROWS / BN)                    // 64
#define NFBLK (NROWS / 128)                   // 64 finalize blocks
#define STAGE_A_BYTES (BM * BK * 2)           // 16384
#define STAGE_BYTES   (2 * STAGE_A_BYTES)     // 32768
#define SMEM_TOTAL    (NSTAGE * STAGE_BYTES)  // 98304
#define LOG2E 1.4426950408889634f
#define LN2   0.6931471805599453f

// ---------------- device scratch ----------------
__device__ __align__(1024) __half g_zh[2 * NROWS * DIM];
__device__ float g_diag[NROWS];               // stores log2e-scaled cosine
__device__ float g_pe[(size_t)JT * NROWS];
__device__ float g_bl[NFBLK];
__device__ float g_bp[NFBLK];
__device__ unsigned int g_cnt;

// ---------------- PTX helpers ----------------
__device__ __forceinline__ uint32_t smem_u32(const void* p) {
    uint32_t a;
    asm("{ .reg .u64 t; cvta.to.shared.u64 t, %1; cvt.u32.u64 %0, t; }" : "=r"(a) : "l"(p));
    return a;
}
#define CPA16(dst, src) \
    asm volatile("cp.async.cg.shared.global [%0], [%1], 16;" :: "r"(dst), "l"(src) : "memory")
#define CPA_COMMIT() asm volatile("cp.async.commit_group;" ::: "memory")
#define CPA_WAIT1()  asm volatile("cp.async.wait_group 1;" ::: "memory")
#define CPA_WAIT0()  asm volatile("cp.async.wait_group 0;" ::: "memory")

__device__ __forceinline__ void ldsm4(uint32_t* r, uint32_t addr) {
    asm volatile("ldmatrix.sync.aligned.m8n8.x4.shared.b16 {%0,%1,%2,%3}, [%4];"
        : "=r"(r[0]), "=r"(r[1]), "=r"(r[2]), "=r"(r[3]) : "r"(addr));
}
__device__ __forceinline__ void mma16816(float* d, const uint32_t* a, const uint32_t* b) {
    asm volatile(
        "mma.sync.aligned.m16n8k16.row.col.f32.f16.f16.f32 "
        "{%0,%1,%2,%3}, {%4,%5,%6,%7}, {%8,%9}, {%0,%1,%2,%3};"
        : "+f"(d[0]), "+f"(d[1]), "+f"(d[2]), "+f"(d[3])
        : "r"(a[0]), "r"(a[1]), "r"(a[2]), "r"(a[3]), "r"(b[0]), "r"(b[1]));
}
// bare ex2 — used in BOTH epilogue and finalize so the diagonal term cancels bitwise
__device__ __forceinline__ float ex2(float x) {
    float r;
    asm("ex2.approx.ftz.f32 %0, %1;" : "=f"(r) : "f"(x));
    return r;
}

// ---------------------------------------------------------------------------
// 1) Fused norms + convert to pre-normalized fp16.
//    x1 rows (row < NROWS) are additionally scaled by log2(e) so the MMA
//    output is log2e*cos and the epilogue exp needs no argument multiply.
// ---------------------------------------------------------------------------
__global__ __launch_bounds__(256) void normconv_kernel(const float* __restrict__ z) {
    if (blockIdx.x == 0 && threadIdx.x == 0) g_cnt = 0;
    int warp = threadIdx.x >> 5, lane = threadIdx.x & 31;
    int row  = blockIdx.x * 8 + warp;
    const float* p = z + (size_t)row * DIM;
    float4 v[8];
    float s = 0.f;
    #pragma unroll
    for (int seg = 0; seg < 4; seg++) {
        #pragma unroll
        for (int h = 0; h < 2; h++) {
            float4 t = *reinterpret_cast<const float4*>(p + seg * 256 + lane * 8 + h * 4);
            v[seg * 2 + h] = t;
            s += t.x * t.x + t.y * t.y + t.z * t.z + t.w * t.w;
        }
    }
    #pragma unroll
    for (int o = 16; o; o >>= 1) s += __shfl_xor_sync(0xffffffffu, s, o);
    float inv = rsqrtf(s);
    if (row < NROWS) inv *= LOG2E;             // fold exp's log2e into x1
    __half* ob = g_zh + (size_t)row * DIM;
    #pragma unroll
    for (int seg = 0; seg < 4; seg++) {
        uint4 pk;
        __half2 h0 = __floats2half2_rn(v[seg*2].x * inv,   v[seg*2].y * inv);
        __half2 h1 = __floats2half2_rn(v[seg*2].z * inv,   v[seg*2].w * inv);
        __half2 h2 = __floats2half2_rn(v[seg*2+1].x * inv, v[seg*2+1].y * inv);
        __half2 h3 = __floats2half2_rn(v[seg*2+1].z * inv, v[seg*2+1].w * inv);
        pk.x = *reinterpret_cast<uint32_t*>(&h0);
        pk.y = *reinterpret_cast<uint32_t*>(&h1);
        pk.z = *reinterpret_cast<uint32_t*>(&h2);
        pk.w = *reinterpret_cast<uint32_t*>(&h3);
        *reinterpret_cast<uint4*>(ob + seg * 256 + lane * 8) = pk;
    }
}

// ---------------------------------------------------------------------------
// 2) HMMA GEMM 128x128x64/iter, 3-stage cp.async, single sync per iter,
//    fused ex2 epilogue (split diag/non-diag paths). 8 warps, 2x4 grid.
// ---------------------------------------------------------------------------
__global__ __launch_bounds__(256, 2) void gemm_kernel() {
    extern __shared__ char smem[];
    const uint32_t sb = smem_u32(smem);
    const int tid = threadIdx.x;
    const int warp = tid >> 5, lane = tid & 31;
    const int wy = warp >> 2, wx = warp & 3;        // 2 x 4 warp grid
    const int bi = blockIdx.y, bj = blockIdx.x;

    const char* Ag = (const char*)(g_zh + (size_t)bi * BM * DIM);
    const char* Bg = (const char*)(g_zh + (size_t)(NROWS + bj * BN) * DIM);

    // cp.async mapping: 128B rows = 8 x 16B chunks; phys = ch ^ (row & 7).
    const int row0 = tid >> 3, ch0 = tid & 7;       // rows 0..31
    uint32_t s_off[4];
    size_t   g_off[4];
    #pragma unroll
    for (int r = 0; r < 4; r++) {
        int row = row0 + r * 32;
        int ph  = ch0 ^ (row & 7);
        s_off[r] = row * 128 + ph * 16;
        g_off[r] = (size_t)row * DIM * 2 + ch0 * 16;
    }

    float acc[4][4][4];
    #pragma unroll
    for (int mt = 0; mt < 4; mt++)
        #pragma unroll
        for (int nt = 0; nt < 4; nt++)
            #pragma unroll
            for (int q = 0; q < 4; q++) acc[mt][nt][q] = 0.f;

    // prologue: stages 0,1
    #pragma unroll
    for (int s = 0; s < NSTAGE - 1; s++) {
        uint32_t As = sb + s * STAGE_BYTES;
        uint32_t Bs = As + STAGE_A_BYTES;
        size_t kb = (size_t)(s * BK) * 2;
        #pragma unroll
        for (int r = 0; r < 4; r++) {
            CPA16(As + s_off[r], Ag + g_off[r] + kb);
            CPA16(Bs + s_off[r], Bg + g_off[r] + kb);
        }
        CPA_COMMIT();
    }

    // ldmatrix lane components
    const int rl  = lane & 15;                  // A row within 16
    const int ahi = lane >> 4;                  // A 16B k-chunk select
    const int nl  = (lane & 7) | ((lane >> 4) << 3);   // B n within 16
    const int bhi = (lane >> 3) & 1;

    for (int kc = 0; kc < NITER; kc++) {
        const int st = kc % NSTAGE;
        if (kc < NITER - 1) { CPA_WAIT1(); } else { CPA_WAIT0(); }
        __syncthreads();
        if (kc + NSTAGE - 1 < NITER) {
            const int sn = (kc + NSTAGE - 1) % NSTAGE;
            uint32_t As = sb + sn * STAGE_BYTES;
            uint32_t Bs = As + STAGE_A_BYTES;
            size_t kb = (size_t)((kc + NSTAGE - 1) * BK) * 2;
            #pragma unroll
            for (int r = 0; r < 4; r++) {
                CPA16(As + s_off[r], Ag + g_off[r] + kb);
                CPA16(Bs + s_off[r], Bg + g_off[r] + kb);
            }
            CPA_COMMIT();
        }
        const uint32_t As = sb + st * STAGE_BYTES;
        const uint32_t Bs = As + STAGE_A_BYTES;
        #pragma unroll
        for (int ks = 0; ks < 4; ks++) {
            uint32_t a[4][4], b[2][4];
            uint32_t a_addr = As + (wy * 64 + rl) * 128 + (((ks * 2 + ahi) ^ (rl & 7)) * 16);
            #pragma unroll
            for (int mt = 0; mt < 4; mt++) ldsm4(a[mt], a_addr + mt * 2048);
            uint32_t b_addr = Bs + (wx * 32 + nl) * 128 + (((ks * 2 + bhi) ^ (nl & 7)) * 16);
            #pragma unroll
            for (int p = 0; p < 2; p++) ldsm4(b[p], b_addr + p * 2048);
            #pragma unroll
            for (int mt = 0; mt < 4; mt++)
                #pragma unroll
                for (int nt = 0; nt < 4; nt++)
                    mma16816(acc[mt][nt], a[mt], &b[nt >> 1][(nt & 1) * 2]);
        }
    }

    // ---------------- epilogue: ex2 row-sums (+ diagonal on diag tiles) ----
    __syncthreads();
    float* sred = (float*)smem;                // 128 rows x 4 wx
    if (bi != bj) {
        // hot path (4032/4096 tiles): no compares, no conditional stores
        #pragma unroll
        for (int mt = 0; mt < 4; mt++) {
            int ra = wy * 64 + mt * 16 + (lane >> 2);
            float sA = 0.f, sB = 0.f;
            #pragma unroll
            for (int nt = 0; nt < 4; nt++) {
                sA += ex2(acc[mt][nt][0]) + ex2(acc[mt][nt][1]);
                sB += ex2(acc[mt][nt][2]) + ex2(acc[mt][nt][3]);
            }
            sA += __shfl_xor_sync(0xffffffffu, sA, 1);
            sA += __shfl_xor_sync(0xffffffffu, sA, 2);
            sB += __shfl_xor_sync(0xffffffffu, sB, 1);
            sB += __shfl_xor_sync(0xffffffffu, sB, 2);
            if ((lane & 3) == 0) {
                sred[ra * 4 + wx] = sA;
                sred[(ra + 8) * 4 + wx] = sB;
            }
        }
    } else {
        // diag path (64 tiles): identical arithmetic + diagonal extraction
        #pragma unroll
        for (int mt = 0; mt < 4; mt++) {
            int ra = wy * 64 + mt * 16 + (lane >> 2);
            float sA = 0.f, sB = 0.f;
            #pragma unroll
            for (int nt = 0; nt < 4; nt++) {
                int c0 = wx * 32 + nt * 8 + 2 * (lane & 3);
                float v0 = acc[mt][nt][0], v1 = acc[mt][nt][1];
                float v2 = acc[mt][nt][2], v3 = acc[mt][nt][3];
                sA += ex2(v0) + ex2(v1);
                sB += ex2(v2) + ex2(v3);
                if (ra == c0)         g_diag[bi * BM + ra] = v0;
                if (ra == c0 + 1)     g_diag[bi * BM + ra] = v1;
                if (ra + 8 == c0)     g_diag[bi * BM + ra + 8] = v2;
                if (ra + 8 == c0 + 1) g_diag[bi * BM + ra + 8] = v3;
            }
            sA += __shfl_xor_sync(0xffffffffu, sA, 1);
            sA += __shfl_xor_sync(0xffffffffu, sA, 2);
            sB += __shfl_xor_sync(0xffffffffu, sB, 1);
            sB += __shfl_xor_sync(0xffffffffu, sB, 2);
            if ((lane & 3) == 0) {
                sred[ra * 4 + wx] = sA;
                sred[(ra + 8) * 4 + wx] = sB;
            }
        }
    }
    __syncthreads();
    if (tid < BM) {
        float s = sred[tid * 4 + 0] + sred[tid * 4 + 1]
                + sred[tid * 4 + 2] + sred[tid * 4 + 3];
        g_pe[(size_t)bj * NROWS + bi * BM + tid] = s;
    }
}

// ---------------------------------------------------------------------------
// 3) Finalize (ALPHA=1 -> alpha=p_ij, BETA=0 -> neg_sim drops).
//    pe = ex2(scaled diag) is bitwise-identical to the epilogue's term, so
//    the row-sum subtraction cancels exactly. pos recovered via * ln2.
// ---------------------------------------------------------------------------
__global__ __launch_bounds__(1024) void finalize_kernel(float* __restrict__ out) {
    __shared__ float spart[8][128];
    __shared__ float sl[128], sp[128];
    __shared__ bool is_last;
    int rl = threadIdx.x & 127, tg = threadIdx.x >> 7;
    int r = blockIdx.x * 128 + rl;
    float se = 0.f;
    #pragma unroll
    for (int t = tg * 8; t < tg * 8 + 8; t++) se += g_pe[(size_t)t * NROWS + r];
    spart[tg][rl] = se;
    __syncthreads();
    if (threadIdx.x < 128) {
        float tot = 0.f;
        #pragma unroll
        for (int t = 0; t < 8; t++) tot += spart[t][rl];
        float dv  = g_diag[r];                 // log2e-scaled cosine
        float pe  = ex2(dv);                   // bitwise-identical to epilogue term
        float pos = dv * LN2;                  // true cosine similarity
        float p   = pe / (tot - pe);
        sl[rl] = -logf(p) - p * pos;
        sp[rl] = p;
    }
    __syncthreads();
    #pragma unroll
    for (int o = 64; o; o >>= 1) {
        if (threadIdx.x < o) {
            sl[threadIdx.x] += sl[threadIdx.x + o];
            sp[threadIdx.x] += sp[threadIdx.x + o];
        }
        __syncthreads();
    }
    if (threadIdx.x == 0) {
        g_bl[blockIdx.x] = sl[0];
        g_bp[blockIdx.x] = sp[0];
        __threadfence();
        unsigned int prev = atomicAdd(&g_cnt, 1u);
        is_last = (prev == NFBLK - 1);
    }
    __syncthreads();
    if (is_last && threadIdx.x == 0) {
        float tl = 0.f, tp = 0.f;
        #pragma unroll
        for (int b = 0; b < NFBLK; b++) { tl += g_bl[b]; tp += g_bp[b]; }
        out[0] = tl / (float)NROWS;
        out[1] = tp / (float)NROWS;
    }
}

// ---------------------------------------------------------------------------
extern "C" void kernel_launch(void* const* d_in, const int* in_sizes, int n_in,
                              void* d_out, int out_size) {
    const float* z = (const float*)d_in[0];
    float* out = (float*)d_out;

    cudaFuncSetAttribute(gemm_kernel, cudaFuncAttributeMaxDynamicSharedMemorySize, SMEM_TOTAL);

    normconv_kernel<<<2 * NROWS / 8, 256>>>(z);
    gemm_kernel<<<dim3(NROWS / BN, NROWS / BM), 256, SMEM_TOTAL>>>();
    finalize_kernel<<<NFBLK, 1024>>>(out);
}